// round 13
// baseline (speedup 1.0000x reference)
#include <cuda_runtime.h>
#include <cuda_fp16.h>
#include <cstdint>

// MeshConvPoint: B=8, C=64, V=25000, D=12, O=64
// k1 (HMMA, single-pass fp16, pipelined): Z[b,v,o'] = sum_c x_h[c,v]*W_h[o,c,k]
//   z0/z1 fp16, 128B rows; staged smem epilogue -> STG.128 (R12, passing).
// k2: out = z0h + (1/deg)*sum z1[nbr] + bias.
//   R13: 2-stage pipelined gathers — while accumulating v_j's 12 rows, the 12
//   loads of v_{j+1} are in flight (MLP 12 -> 24; regs float above 32).

#define BB 8
#define CC 64
#define VV 25000
#define DD 12
#define OO 64
#define NT 391            // ceil(VV/64) v-tiles
#define GX 74             // k1 grid.x (74*8=592 blocks = 4/SM)

__device__ __half g_z0[(size_t)BB * VV * 64];          // 25.6 MB fp16
__device__ __half g_z1[((size_t)BB * VV + 1) * 64];    // 25.6 MB + zero row (bss-zeroed, never written)

__device__ __forceinline__ uint32_t smem_u32(const void* p) {
    uint32_t a;
    asm("{ .reg .u64 t; cvta.to.shared.u64 t, %1; cvt.u32.u64 %0, t; }" : "=r"(a) : "l"(p));
    return a;
}
__device__ __forceinline__ void ldsm_x4_t(uint32_t& r0, uint32_t& r1, uint32_t& r2, uint32_t& r3,
                                          uint32_t addr) {
    asm volatile("ldmatrix.sync.aligned.m8n8.x4.trans.shared.b16 {%0,%1,%2,%3}, [%4];"
                 : "=r"(r0), "=r"(r1), "=r"(r2), "=r"(r3) : "r"(addr));
}
__device__ __forceinline__ void ldsm_x2(uint32_t& r0, uint32_t& r1, uint32_t addr) {
    asm volatile("ldmatrix.sync.aligned.m8n8.x2.shared.b16 {%0,%1}, [%2];"
                 : "=r"(r0), "=r"(r1) : "r"(addr));
}
__device__ __forceinline__ void mma16816(float* c, const uint32_t* a, const uint32_t* bfr) {
    asm volatile(
        "mma.sync.aligned.m16n8k16.row.col.f32.f16.f16.f32 "
        "{%0,%1,%2,%3}, {%4,%5,%6,%7}, {%8,%9}, {%0,%1,%2,%3};"
        : "+f"(c[0]), "+f"(c[1]), "+f"(c[2]), "+f"(c[3])
        : "r"(a[0]), "r"(a[1]), "r"(a[2]), "r"(a[3]), "r"(bfr[0]), "r"(bfr[1]));
}
__device__ __forceinline__ uint32_t packf2(float a, float b) {
    __half2 h = __floats2half2_rn(a, b);             // single F2FP.PACK
    return *reinterpret_cast<uint32_t*>(&h);
}

// smem layout (bytes), row stride 144 -> conflict-free ldmatrix / staging
#define LDB    144
#define SM_BHI 0
#define SM_A0  (SM_BHI + 128 * LDB)       // 18432
#define SM_A1  (SM_A0 + 64 * LDB)        // 27648
#define SM_STG (SM_A1 + 64 * LDB)        // 36864: 64 x 72 halves staging
#define SM_TOTAL (SM_STG + 64 * LDB)     // 46080 bytes -> 4 CTAs/SM

// ---------------------------------------------------------------------------
// Kernel 1: 256 threads (8 warps, warp-grid 2m x 4n). Tile = 64v x 128o'.
// Block loops over v-tiles t = bx, bx+GX, ... with double-buffered A.
// ---------------------------------------------------------------------------
__global__ __launch_bounds__(256, 4) void k1_gemm(const float* __restrict__ x,
                                                  const float* __restrict__ W) {
    extern __shared__ char smem[];
    const uint32_t sb = smem_u32(smem);
    const int tid = threadIdx.x, wid = tid >> 5, lane = tid & 31;
    const int b = blockIdx.y, bx = blockIdx.x;
    const int mh = wid >> 2, nq = wid & 3;

    // ---- W prep (once per block): 1024 items = 128 o'-rows x 8 c-groups ----
    for (int i = tid; i < 1024; i += 256) {
        int op = i >> 3, g = i & 7;       // B-row o' = kk*64+o, c-group
        int o = op & 63, kk = op >> 6;
        const float* wp = W + ((size_t)o * 64 + g * 8) * 2 + kk;
        uint4 u;
        u.x = packf2(wp[0],  wp[2]);
        u.y = packf2(wp[4],  wp[6]);
        u.z = packf2(wp[8],  wp[10]);
        u.w = packf2(wp[12], wp[14]);
        *reinterpret_cast<uint4*>(smem + SM_BHI + (uint32_t)op * LDB + g * 16) = u;
    }

    const float* xb = x + (size_t)b * CC * VV;
    const int c  = tid >> 2;              // x row this thread loads/converts
    const int vs = (tid & 3) * 16;        // 16 v's = 4 float4

    float4 f[4];
    {
        const int v0 = bx * 64;
        #pragma unroll
        for (int j = 0; j < 4; j++) {
            int vbse = v0 + vs + 4 * j;
            f[j] = (vbse + 3 < VV) ? *reinterpret_cast<const float4*>(xb + (size_t)c * VV + vbse)
                                   : make_float4(0.f, 0.f, 0.f, 0.f);
        }
    }
    {
        uint32_t off = SM_A0 + (uint32_t)c * LDB + vs * 2;
        #pragma unroll
        for (int j = 0; j < 4; j++)
            *reinterpret_cast<uint2*>(smem + off + j * 8) =
                make_uint2(packf2(f[j].x, f[j].y), packf2(f[j].z, f[j].w));
    }

    const int r  = lane >> 2, cp = (lane & 3) * 2;
    __half* z0p = g_z0 + (size_t)b * VV * 64;
    __half* z1p = g_z1 + (size_t)b * VV * 64;
    __half* stg = reinterpret_cast<__half*>(smem + SM_STG);  // [64][72]

    int buf = 0;
    for (int t = bx; t < NT; t += GX) {
        __syncthreads();                  // A[buf] (and W on iter 0) visible
        const int tn = t + GX;

        // prefetch next tile's x into regs (in flight during MMA)
        if (tn < NT) {
            const int v0n = tn * 64;
            #pragma unroll
            for (int j = 0; j < 4; j++) {
                int vbse = v0n + vs + 4 * j;
                f[j] = (vbse + 3 < VV) ? *reinterpret_cast<const float4*>(xb + (size_t)c * VV + vbse)
                                       : make_float4(0.f, 0.f, 0.f, 0.f);
            }
        }

        // ---- MMA on A[buf]: single fp16 pass, K=64 in 4 steps ----
        float acc[2][4][4];
        #pragma unroll
        for (int mt = 0; mt < 2; mt++)
            #pragma unroll
            for (int nt = 0; nt < 4; nt++)
                #pragma unroll
                for (int q = 0; q < 4; q++) acc[mt][nt][q] = 0.0f;

        const uint32_t Ab = sb + (buf ? SM_A1 : SM_A0);
        const uint32_t Bb = sb + SM_BHI;
        #pragma unroll
        for (int ks = 0; ks < 4; ks++) {
            uint32_t af[2][4];
            #pragma unroll
            for (int mt = 0; mt < 2; mt++) {
                uint32_t r0, r1, r2, r3;
                uint32_t addr = Ab + (ks * 16 + (lane & 15)) * LDB
                              + (mh * 32 + mt * 16) * 2 + (lane >> 4) * 16;
                ldsm_x4_t(r0, r1, r2, r3, addr);
                af[mt][0] = r0; af[mt][1] = r2; af[mt][2] = r1; af[mt][3] = r3;
            }
            uint32_t bf[4][2];
            #pragma unroll
            for (int nt = 0; nt < 4; nt++) {
                uint32_t addr = Bb + (nq * 32 + nt * 8 + (lane & 7)) * LDB
                              + ks * 32 + ((lane >> 3) & 1) * 16;
                ldsm_x2(bf[nt][0], bf[nt][1], addr);
            }
            #pragma unroll
            for (int mt = 0; mt < 2; mt++)
                #pragma unroll
                for (int nt = 0; nt < 4; nt++)
                    mma16816(acc[mt][nt], af[mt], bf[nt]);
        }

        // fill other buffer with prefetched tile
        if (tn < NT) {
            uint32_t off = (buf ? SM_A0 : SM_A1) + (uint32_t)c * LDB + vs * 2;
            #pragma unroll
            for (int j = 0; j < 4; j++)
                *reinterpret_cast<uint2*>(smem + off + j * 8) =
                    make_uint2(packf2(f[j].x, f[j].y), packf2(f[j].z, f[j].w));
        }

        // ---- epilogue: stage each z-half in smem, store 128B rows (STG.128) ----
        const int v0 = t * 64;
        #pragma unroll
        for (int hz = 0; hz < 2; hz++) {                 // 0 -> z0h, 1 -> z1
            __syncthreads();                             // stage free
            if ((nq >> 1) == hz) {
                const int ol = (nq & 1) * 32;
                #pragma unroll
                for (int mt = 0; mt < 2; mt++) {
                    const int vl = mh * 32 + mt * 16 + r;
                    #pragma unroll
                    for (int nt = 0; nt < 4; nt++) {
                        const int oo = ol + nt * 8 + cp;
                        *reinterpret_cast<__half2*>(&stg[vl * 72 + oo]) =
                            __floats2half2_rn(acc[mt][nt][0], acc[mt][nt][1]);
                        *reinterpret_cast<__half2*>(&stg[(vl + 8) * 72 + oo]) =
                            __floats2half2_rn(acc[mt][nt][2], acc[mt][nt][3]);
                    }
                }
            }
            __syncthreads();                             // stage filled
            // copy-out: 64 rows x 8 uint4 chunks = 512 items (2 per thread)
            __half* dst = hz ? z1p : z0p;
            #pragma unroll
            for (int i = tid; i < 512; i += 256) {
                const int row = i >> 3, ch = i & 7;
                const int v1 = v0 + row;
                if (v1 < VV) {
                    uint4 u = *reinterpret_cast<uint4*>(&stg[row * 72 + ch * 8]);
                    *reinterpret_cast<uint4*>(dst + (size_t)v1 * 64 + ch * 8) = u;
                }
            }
        }
        buf ^= 1;
    }
}

// ---------------------------------------------------------------------------
// Kernel 2: 32 v per block, 256 threads. Branch-free gathers (zero-row pad),
// pre-scaled 32-bit offsets. 2-stage pipelined: accumulate v_j while v_{j+1}
// loads are in flight (MLP ~24/warp). launch_bounds lets regs float (~56).
// ---------------------------------------------------------------------------
__global__ __launch_bounds__(256) void k2_gather(const int* __restrict__ nbr,
                                                 const int* __restrict__ deg,
                                                 const float* __restrict__ bias,
                                                 float* __restrict__ out) {
    __shared__ int   rows32[32][DD];   // safe z1 row index * 32
    __shared__ int   deg_s[32];
    __shared__ float ob[64][33];

    const int b = blockIdx.y, v0 = blockIdx.x * 32, tid = threadIdx.x;

    if (tid < 32) {
        int gv = v0 + tid;
        deg_s[tid] = (gv < VV) ? deg[(size_t)b * VV + gv] : 0;
    }
    __syncthreads();
    for (int i = tid; i < 32 * DD; i += 256) {
        int v = i / DD, d = i % DD;
        int gv = v0 + v;
        int rr = BB * VV;                                 // zero row
        if (gv < VV && d < deg_s[v])
            rr = b * VV + nbr[((size_t)b * VV + gv) * DD + d];
        rows32[v][d] = rr * 32;
    }
    __syncthreads();

    const int w = tid >> 5, lane = tid & 31;
    const __half2* z1p = reinterpret_cast<const __half2*>(g_z1);
    const __half2* z0p = reinterpret_cast<const __half2*>(g_z0);
    const float2 bia = *reinterpret_cast<const float2*>(bias + 2 * lane);
    const __half2 hz0 = __halves2half2(__ushort_as_half(0), __ushort_as_half(0));

    // hoist all 4 z0h loads (latency rides under the first gather round)
    __half2 sh[4];
    #pragma unroll
    for (int j = 0; j < 4; j++) {
        const int gv = v0 + w * 4 + j;
        sh[j] = (gv < VV) ? z0p[((size_t)b * VV + gv) * 32 + lane] : hz0;
    }

    // 2-stage pipeline over the 4 v's of this warp
    __half2 g[2][DD];
    #pragma unroll
    for (int d = 0; d < DD; d++)
        g[0][d] = z1p[rows32[w * 4][d] + lane];

    #pragma unroll
    for (int j = 0; j < 4; j++) {
        const int cur = j & 1, nxt = cur ^ 1;
        if (j < 3) {                                      // issue next v's 12 loads
            #pragma unroll
            for (int d = 0; d < DD; d++)
                g[nxt][d] = z1p[rows32[w * 4 + j + 1][d] + lane];
        }
        __half2 a = hz0;                                  // accumulate current v
        #pragma unroll
        for (int d = 0; d < DD; d++)
            a = __hadd2(a, g[cur][d]);

        const int vl = w * 4 + j;
        const int gv = v0 + vl;
        if (gv < VV) {
            float2 af = __half22float2(a);
            float2 s  = __half22float2(sh[j]);
            float inv = 1.0f / (float)max(deg_s[vl], 1);
            ob[2 * lane][vl]     = s.x + af.x * inv + bia.x;
            ob[2 * lane + 1][vl] = s.y + af.y * inv + bia.y;
        }
    }
    __syncthreads();

    for (int i = tid; i < 64 * 32; i += 256) {
        int o = i >> 5, v = i & 31;
        int gv = v0 + v;
        if (gv < VV)
            out[((size_t)b * OO + o) * VV + gv] = ob[o][v];
    }
}

extern "C" void kernel_launch(void* const* d_in, const int* in_sizes, int n_in,
                              void* d_out, int out_size) {
    const float* x    = (const float*)d_in[0];
    const int*   nbr  = (const int*)d_in[1];
    const int*   deg  = (const int*)d_in[2];
    const float* W    = (const float*)d_in[3];
    const float* bias = (const float*)d_in[4];
    float*       out  = (float*)d_out;

    cudaFuncSetAttribute(k1_gemm, cudaFuncAttributeMaxDynamicSharedMemorySize, SM_TOTAL);

    dim3 g1(GX, BB);
    k1_gemm<<<g1, 256, SM_TOTAL>>>(x, W);

    dim3 g2((VV + 31) / 32, BB);
    k2_gather<<<g2, 256>>>(nbr, deg, bias, out);
}

// round 14
// speedup vs baseline: 1.1416x; 1.1416x over previous
#include <cuda_runtime.h>
#include <cuda_fp16.h>
#include <cstdint>

// MeshConvPoint: B=8, C=64, V=25000, D=12, O=64
// k1 (HMMA, single-pass fp16, pipelined): Z[b,v,o'] = sum_c x_h[c,v]*W_h[o,c,k]
//   z0/z1 fp16, 128B rows; staged smem epilogue -> STG.128 (R12, passing).
// k2 (R14): lane-split gathers. Lane l serves v = w*4+(l>>3), o-chunk (l&7)*8.
//   One LDG.128 per (warp,d) covers all 4 v's -> 12 LDG/warp (was 48), one
//   accumulation round (was 4 serial), regs stay ~36 (R13 lesson: registers
//   spent on MLP kill occupancy and lose).

#define BB 8
#define CC 64
#define VV 25000
#define DD 12
#define OO 64
#define NT 391            // ceil(VV/64) v-tiles
#define GX 74             // k1 grid.x (74*8=592 blocks = 4/SM)

__device__ __half g_z0[(size_t)BB * VV * 64];          // 25.6 MB fp16
__device__ __half g_z1[((size_t)BB * VV + 1) * 64];    // 25.6 MB + zero row (bss-zeroed, never written)

__device__ __forceinline__ uint32_t smem_u32(const void* p) {
    uint32_t a;
    asm("{ .reg .u64 t; cvta.to.shared.u64 t, %1; cvt.u32.u64 %0, t; }" : "=r"(a) : "l"(p));
    return a;
}
__device__ __forceinline__ void ldsm_x4_t(uint32_t& r0, uint32_t& r1, uint32_t& r2, uint32_t& r3,
                                          uint32_t addr) {
    asm volatile("ldmatrix.sync.aligned.m8n8.x4.trans.shared.b16 {%0,%1,%2,%3}, [%4];"
                 : "=r"(r0), "=r"(r1), "=r"(r2), "=r"(r3) : "r"(addr));
}
__device__ __forceinline__ void ldsm_x2(uint32_t& r0, uint32_t& r1, uint32_t addr) {
    asm volatile("ldmatrix.sync.aligned.m8n8.x2.shared.b16 {%0,%1}, [%2];"
                 : "=r"(r0), "=r"(r1) : "r"(addr));
}
__device__ __forceinline__ void mma16816(float* c, const uint32_t* a, const uint32_t* bfr) {
    asm volatile(
        "mma.sync.aligned.m16n8k16.row.col.f32.f16.f16.f32 "
        "{%0,%1,%2,%3}, {%4,%5,%6,%7}, {%8,%9}, {%0,%1,%2,%3};"
        : "+f"(c[0]), "+f"(c[1]), "+f"(c[2]), "+f"(c[3])
        : "r"(a[0]), "r"(a[1]), "r"(a[2]), "r"(a[3]), "r"(bfr[0]), "r"(bfr[1]));
}
__device__ __forceinline__ uint32_t packf2(float a, float b) {
    __half2 h = __floats2half2_rn(a, b);             // single F2FP.PACK
    return *reinterpret_cast<uint32_t*>(&h);
}
__device__ __forceinline__ __half2 u2h2(uint32_t u) { return *reinterpret_cast<__half2*>(&u); }

// smem layout (bytes), row stride 144 -> conflict-free ldmatrix / staging
#define LDB    144
#define SM_BHI 0
#define SM_A0  (SM_BHI + 128 * LDB)       // 18432
#define SM_A1  (SM_A0 + 64 * LDB)        // 27648
#define SM_STG (SM_A1 + 64 * LDB)        // 36864: 64 x 72 halves staging
#define SM_TOTAL (SM_STG + 64 * LDB)     // 46080 bytes -> 4 CTAs/SM

// ---------------------------------------------------------------------------
// Kernel 1: 256 threads (8 warps, warp-grid 2m x 4n). Tile = 64v x 128o'.
// Block loops over v-tiles t = bx, bx+GX, ... with double-buffered A.
// ---------------------------------------------------------------------------
__global__ __launch_bounds__(256, 4) void k1_gemm(const float* __restrict__ x,
                                                  const float* __restrict__ W) {
    extern __shared__ char smem[];
    const uint32_t sb = smem_u32(smem);
    const int tid = threadIdx.x, wid = tid >> 5, lane = tid & 31;
    const int b = blockIdx.y, bx = blockIdx.x;
    const int mh = wid >> 2, nq = wid & 3;

    // ---- W prep (once per block): 1024 items = 128 o'-rows x 8 c-groups ----
    for (int i = tid; i < 1024; i += 256) {
        int op = i >> 3, g = i & 7;       // B-row o' = kk*64+o, c-group
        int o = op & 63, kk = op >> 6;
        const float* wp = W + ((size_t)o * 64 + g * 8) * 2 + kk;
        uint4 u;
        u.x = packf2(wp[0],  wp[2]);
        u.y = packf2(wp[4],  wp[6]);
        u.z = packf2(wp[8],  wp[10]);
        u.w = packf2(wp[12], wp[14]);
        *reinterpret_cast<uint4*>(smem + SM_BHI + (uint32_t)op * LDB + g * 16) = u;
    }

    const float* xb = x + (size_t)b * CC * VV;
    const int c  = tid >> 2;              // x row this thread loads/converts
    const int vs = (tid & 3) * 16;        // 16 v's = 4 float4

    float4 f[4];
    {
        const int v0 = bx * 64;
        #pragma unroll
        for (int j = 0; j < 4; j++) {
            int vbse = v0 + vs + 4 * j;
            f[j] = (vbse + 3 < VV) ? *reinterpret_cast<const float4*>(xb + (size_t)c * VV + vbse)
                                   : make_float4(0.f, 0.f, 0.f, 0.f);
        }
    }
    {
        uint32_t off = SM_A0 + (uint32_t)c * LDB + vs * 2;
        #pragma unroll
        for (int j = 0; j < 4; j++)
            *reinterpret_cast<uint2*>(smem + off + j * 8) =
                make_uint2(packf2(f[j].x, f[j].y), packf2(f[j].z, f[j].w));
    }

    const int r  = lane >> 2, cp = (lane & 3) * 2;
    __half* z0p = g_z0 + (size_t)b * VV * 64;
    __half* z1p = g_z1 + (size_t)b * VV * 64;
    __half* stg = reinterpret_cast<__half*>(smem + SM_STG);  // [64][72]

    int buf = 0;
    for (int t = bx; t < NT; t += GX) {
        __syncthreads();                  // A[buf] (and W on iter 0) visible
        const int tn = t + GX;

        // prefetch next tile's x into regs (in flight during MMA)
        if (tn < NT) {
            const int v0n = tn * 64;
            #pragma unroll
            for (int j = 0; j < 4; j++) {
                int vbse = v0n + vs + 4 * j;
                f[j] = (vbse + 3 < VV) ? *reinterpret_cast<const float4*>(xb + (size_t)c * VV + vbse)
                                       : make_float4(0.f, 0.f, 0.f, 0.f);
            }
        }

        // ---- MMA on A[buf]: single fp16 pass, K=64 in 4 steps ----
        float acc[2][4][4];
        #pragma unroll
        for (int mt = 0; mt < 2; mt++)
            #pragma unroll
            for (int nt = 0; nt < 4; nt++)
                #pragma unroll
                for (int q = 0; q < 4; q++) acc[mt][nt][q] = 0.0f;

        const uint32_t Ab = sb + (buf ? SM_A1 : SM_A0);
        const uint32_t Bb = sb + SM_BHI;
        #pragma unroll
        for (int ks = 0; ks < 4; ks++) {
            uint32_t af[2][4];
            #pragma unroll
            for (int mt = 0; mt < 2; mt++) {
                uint32_t r0, r1, r2, r3;
                uint32_t addr = Ab + (ks * 16 + (lane & 15)) * LDB
                              + (mh * 32 + mt * 16) * 2 + (lane >> 4) * 16;
                ldsm_x4_t(r0, r1, r2, r3, addr);
                af[mt][0] = r0; af[mt][1] = r2; af[mt][2] = r1; af[mt][3] = r3;
            }
            uint32_t bf[4][2];
            #pragma unroll
            for (int nt = 0; nt < 4; nt++) {
                uint32_t addr = Bb + (nq * 32 + nt * 8 + (lane & 7)) * LDB
                              + ks * 32 + ((lane >> 3) & 1) * 16;
                ldsm_x2(bf[nt][0], bf[nt][1], addr);
            }
            #pragma unroll
            for (int mt = 0; mt < 2; mt++)
                #pragma unroll
                for (int nt = 0; nt < 4; nt++)
                    mma16816(acc[mt][nt], af[mt], bf[nt]);
        }

        // fill other buffer with prefetched tile
        if (tn < NT) {
            uint32_t off = (buf ? SM_A0 : SM_A1) + (uint32_t)c * LDB + vs * 2;
            #pragma unroll
            for (int j = 0; j < 4; j++)
                *reinterpret_cast<uint2*>(smem + off + j * 8) =
                    make_uint2(packf2(f[j].x, f[j].y), packf2(f[j].z, f[j].w));
        }

        // ---- epilogue: stage each z-half in smem, store 128B rows (STG.128) ----
        const int v0 = t * 64;
        #pragma unroll
        for (int hz = 0; hz < 2; hz++) {                 // 0 -> z0h, 1 -> z1
            __syncthreads();                             // stage free
            if ((nq >> 1) == hz) {
                const int ol = (nq & 1) * 32;
                #pragma unroll
                for (int mt = 0; mt < 2; mt++) {
                    const int vl = mh * 32 + mt * 16 + r;
                    #pragma unroll
                    for (int nt = 0; nt < 4; nt++) {
                        const int oo = ol + nt * 8 + cp;
                        *reinterpret_cast<__half2*>(&stg[vl * 72 + oo]) =
                            __floats2half2_rn(acc[mt][nt][0], acc[mt][nt][1]);
                        *reinterpret_cast<__half2*>(&stg[(vl + 8) * 72 + oo]) =
                            __floats2half2_rn(acc[mt][nt][2], acc[mt][nt][3]);
                    }
                }
            }
            __syncthreads();                             // stage filled
            // copy-out: 64 rows x 8 uint4 chunks = 512 items (2 per thread)
            __half* dst = hz ? z1p : z0p;
            #pragma unroll
            for (int i = tid; i < 512; i += 256) {
                const int row = i >> 3, ch = i & 7;
                const int v1 = v0 + row;
                if (v1 < VV) {
                    uint4 u = *reinterpret_cast<uint4*>(&stg[row * 72 + ch * 8]);
                    *reinterpret_cast<uint4*>(dst + (size_t)v1 * 64 + ch * 8) = u;
                }
            }
        }
        buf ^= 1;
    }
}

// ---------------------------------------------------------------------------
// Kernel 2: 32 v per block, 256 threads. Lane-split gathers: lane l serves
// v = w*4 + (l>>3), o-chunk (l&7)*8. 12 LDG.128 per warp total.
// ---------------------------------------------------------------------------
__global__ __launch_bounds__(256) void k2_gather(const int* __restrict__ nbr,
                                                 const int* __restrict__ deg,
                                                 const float* __restrict__ bias,
                                                 float* __restrict__ out) {
    __shared__ int   rows8[32][DD];    // safe z1 row index * 8 (uint4 units)
    __shared__ int   deg_s[32];
    __shared__ float bias_s[64];
    __shared__ float ob[64][33];

    const int b = blockIdx.y, v0 = blockIdx.x * 32, tid = threadIdx.x;

    if (tid < 32) {
        int gv = v0 + tid;
        deg_s[tid] = (gv < VV) ? deg[(size_t)b * VV + gv] : 0;
    }
    if (tid >= 64 && tid < 128) bias_s[tid - 64] = bias[tid - 64];
    __syncthreads();
    for (int i = tid; i < 32 * DD; i += 256) {
        int v = i / DD, d = i % DD;
        int gv = v0 + v;
        int rr = BB * VV;                                 // zero row
        if (gv < VV && d < deg_s[v])
            rr = b * VV + nbr[((size_t)b * VV + gv) * DD + d];
        rows8[v][d] = rr * 8;
    }
    __syncthreads();

    const int w = tid >> 5, lane = tid & 31;
    const int vl = w * 4 + (lane >> 3);   // this lane's v (0..31)
    const int oc = lane & 7;              // o-chunk: o = oc*8 .. oc*8+7
    const int gv = v0 + vl;
    const uint4* z1q = reinterpret_cast<const uint4*>(g_z1);
    const uint4* z0q = reinterpret_cast<const uint4*>(g_z0);

    // self row chunk (8 halves) — latency rides under the gathers
    uint4 s0u = make_uint4(0, 0, 0, 0);
    if (gv < VV) s0u = z0q[((size_t)b * VV + gv) * 8 + oc];

    const __half2 hz0 = __halves2half2(__ushort_as_half(0), __ushort_as_half(0));
    __half2 a0 = hz0, a1 = hz0, a2 = hz0, a3 = hz0;

    #pragma unroll
    for (int d = 0; d < DD; d++) {
        uint4 u = z1q[rows8[vl][d] + oc];                 // 1 LDG.128 serves 4 v's/warp
        a0 = __hadd2(a0, u2h2(u.x));
        a1 = __hadd2(a1, u2h2(u.y));
        a2 = __hadd2(a2, u2h2(u.z));
        a3 = __hadd2(a3, u2h2(u.w));
    }

    if (gv < VV) {
        const float inv = 1.0f / (float)max(deg_s[vl], 1);
        const int ob0 = oc * 8;
        float2 f0 = __half22float2(a0), f1 = __half22float2(a1);
        float2 f2 = __half22float2(a2), f3 = __half22float2(a3);
        float2 s0 = __half22float2(u2h2(s0u.x)), s1 = __half22float2(u2h2(s0u.y));
        float2 s2 = __half22float2(u2h2(s0u.z)), s3 = __half22float2(u2h2(s0u.w));
        ob[ob0 + 0][vl] = s0.x + f0.x * inv + bias_s[ob0 + 0];
        ob[ob0 + 1][vl] = s0.y + f0.y * inv + bias_s[ob0 + 1];
        ob[ob0 + 2][vl] = s1.x + f1.x * inv + bias_s[ob0 + 2];
        ob[ob0 + 3][vl] = s1.y + f1.y * inv + bias_s[ob0 + 3];
        ob[ob0 + 4][vl] = s2.x + f2.x * inv + bias_s[ob0 + 4];
        ob[ob0 + 5][vl] = s2.y + f2.y * inv + bias_s[ob0 + 5];
        ob[ob0 + 6][vl] = s3.x + f3.x * inv + bias_s[ob0 + 6];
        ob[ob0 + 7][vl] = s3.y + f3.y * inv + bias_s[ob0 + 7];
    }
    __syncthreads();

    for (int i = tid; i < 64 * 32; i += 256) {
        int o = i >> 5, v = i & 31;
        int gv2 = v0 + v;
        if (gv2 < VV)
            out[((size_t)b * OO + o) * VV + gv2] = ob[o][v];
    }
}

extern "C" void kernel_launch(void* const* d_in, const int* in_sizes, int n_in,
                              void* d_out, int out_size) {
    const float* x    = (const float*)d_in[0];
    const int*   nbr  = (const int*)d_in[1];
    const int*   deg  = (const int*)d_in[2];
    const float* W    = (const float*)d_in[3];
    const float* bias = (const float*)d_in[4];
    float*       out  = (float*)d_out;

    cudaFuncSetAttribute(k1_gemm, cudaFuncAttributeMaxDynamicSharedMemorySize, SM_TOTAL);

    dim3 g1(GX, BB);
    k1_gemm<<<g1, 256, SM_TOTAL>>>(x, W);

    dim3 g2((VV + 31) / 32, BB);
    k2_gather<<<g2, 256>>>(nbr, deg, bias, out);
}